// round 9
// baseline (speedup 1.0000x reference)
#include <cuda_runtime.h>
#include <math.h>

#define BB 4
#define NN 4096
#define KK 16
#define NB 32          // 2k neighbors per query
#define FULL 0xffffffffu

typedef unsigned long long u64;

// ---------------- scratch (__device__ globals; no allocation allowed) -------
__device__ float g_feats[BB * NN * NB * 4];                 // {rx,ry,rz,dist} per token, 8MB

// ---------------- f32x2 helpers --------------------------------------------
__device__ __forceinline__ u64 ffma2(u64 a, u64 b, u64 c) {
    u64 d;
    asm("fma.rn.f32x2 %0, %1, %2, %3;" : "=l"(d) : "l"(a), "l"(b), "l"(c));
    return d;
}
__device__ __forceinline__ u64 pack2(float x) {
    u64 r;
    unsigned xu = __float_as_uint(x);
    asm("mov.b64 %0, {%1, %1};" : "=l"(r) : "r"(xu));
    return r;
}
__device__ __forceinline__ void unpack2(u64 v, float& lo, float& hi) {
    unsigned a, b;
    asm("mov.b64 {%0, %1}, %2;" : "=r"(a), "=r"(b) : "l"(v));
    lo = __uint_as_float(a);
    hi = __uint_as_float(b);
}

// ---------------- kNN: warp per query, warp-collective top-16 --------------
// (unchanged from best passing round)
__global__ __launch_bounds__(512) void knn_kernel(
    const float* __restrict__ p1, const float* __restrict__ p2)
{
    extern __shared__ float4 tile[];       // 4096 x {x,y,z,|r|^2}
    const int lane = threadIdx.x & 31;
    const int warp = threadIdx.x >> 5;
    const int b = blockIdx.y;
    const int set = blockIdx.z;

    const float* qb = p1 + b * 3 * NN;
    const float* rb = (set == 0 ? p1 : p2) + b * 3 * NN;

    for (int j = threadIdx.x; j < NN; j += 512) {
        float rx = rb[j], ry = rb[NN + j], rz = rb[2 * NN + j];
        tile[j] = make_float4(rx, ry, rz, rx * rx + ry * ry + rz * rz);
    }
    __syncthreads();

    const int qi = blockIdx.x * 16 + warp;
    const float qx = qb[qi], qy = qb[NN + qi], qz = qb[2 * NN + qi];
    const float qq = qx * qx + qy * qy + qz * qz;

    float ld;
    int   li;
    {
        float4 c = tile[lane];
        float dot = qx * c.x + qy * c.y + qz * c.z;
        ld = fmaf(-2.0f, dot, qq) + c.w;
        li = lane;
#pragma unroll
        for (int k = 2; k <= 32; k <<= 1) {
#pragma unroll
            for (int j = k >> 1; j > 0; j >>= 1) {
                float od = __shfl_xor_sync(FULL, ld, j);
                int   oi = __shfl_xor_sync(FULL, li, j);
                bool up    = ((lane & k) == 0);
                bool lower = ((lane & j) == 0);
                bool lt = (od < ld) || (od == ld && oi < li);
                bool takeOther = (lt == (lower == up));
                ld = takeOther ? od : ld;
                li = takeOther ? oi : li;
            }
        }
    }
    float thresh = __shfl_sync(FULL, ld, 15);

#pragma unroll 2
    for (int t = 1; t < NN / 32; t++) {
        const int j = t * 32 + lane;
        float4 c = tile[j];
        float dot = qx * c.x + qy * c.y + qz * c.z;
        float d2 = fmaf(-2.0f, dot, qq) + c.w;
        unsigned mask = __ballot_sync(FULL, d2 < thresh);
        if (mask) {
            do {
                int src = __ffs(mask) - 1;
                mask &= mask - 1;
                float xd = __shfl_sync(FULL, d2, src);
                int   xi = __shfl_sync(FULL, j, src);
                float pd = __shfl_up_sync(FULL, ld, 1);
                int   pi = __shfl_up_sync(FULL, li, 1);
                bool take  = (xd < ld);
                bool shift = (lane > 0) && (xd < pd);
                ld = take ? (shift ? pd : xd) : ld;
                li = take ? (shift ? pi : xi) : li;
            } while (mask);
            thresh = __shfl_sync(FULL, ld, 15);
        }
    }

    if (lane < KK) {
        float4 c = tile[li];
        float rx = c.x - qx, ry = c.y - qy, rz = c.z - qz;
        float d2r = rx * rx + ry * ry + rz * rz;
        float dist = sqrtf(fmaxf(d2r, 1e-12f));
        ((float4*)g_feats)[((size_t)(b * NN + qi)) * NB + set * KK + lane] =
            make_float4(rx, ry, rz, dist);
    }
}

// ---------------- fused fold + MLP + max + softmax + weighted sum ----------
// 512 threads per 256 tokens, thread = 8 output channels x 4 tokens:
//   grp = tid & 63 (token group), g = tid >> 6 (channel group, 0..7)
// acc = 16 u64 (32 regs) -> forced <=64 regs -> 2 CTAs/SM = 32 warps/SM.
#define MT 256                      // tokens per MLP block
#define MTHR 512                    // threads per MLP block
#define S_W0  0
#define S_C0  256
#define S_C1  320
#define S_C2  384                   // 128 entries
#define S_SC2 512                   // 64 scales for out-ch 64..127 (refold)
#define S_WA  576                   // W1, then W2 h=1
#define S_WB  (S_WA + 4096)         // W2 h=0
#define S_ACT (S_WB + 4096)         // [64][MT]
#define SMEM_FLOATS (S_ACT + 64 * MT)
#define SMEM_BYTES  (SMEM_FLOATS * 4)

__global__ __launch_bounds__(MTHR, 2) void mlp_kernel(
    const float* __restrict__ p1, float* __restrict__ out,
    const float* __restrict__ w0, const float* __restrict__ b0,
    const float* __restrict__ ga0, const float* __restrict__ be0,
    const float* __restrict__ mm0, const float* __restrict__ vv0,
    const float* __restrict__ w1, const float* __restrict__ b1,
    const float* __restrict__ ga1, const float* __restrict__ be1,
    const float* __restrict__ mm1, const float* __restrict__ vv1,
    const float* __restrict__ w2, const float* __restrict__ b2,
    const float* __restrict__ ga2, const float* __restrict__ be2,
    const float* __restrict__ mm2, const float* __restrict__ vv2)
{
    extern __shared__ float sm[];
    float* sAct = sm + S_ACT;

    const int tid = threadIdx.x;

    // ---- in-block BN fold ----
    if (tid < 64) {
        float s = ga0[tid] * rsqrtf(vv0[tid] + 1e-3f);
        sm[S_C0 + tid] = (b0[tid] - mm0[tid]) * s + be0[tid];
    } else if (tid < 128) {
        int o = tid - 64;
        float s = ga1[o] * rsqrtf(vv1[o] + 1e-3f);
        sm[S_C1 + o] = (b1[o] - mm1[o]) * s + be1[o];
    } else if (tid < 256) {
        int o = tid - 128;
        float s = ga2[o] * rsqrtf(vv2[o] + 1e-3f);
        sm[S_C2 + o] = (b2[o] - mm2[o]) * s + be2[o];
        if (o >= 64) sm[S_SC2 + o - 64] = s;
    }
    if (tid < 256) {       // W0 [4][64]
        int c = tid >> 6, o = tid & 63;
        float s = ga0[o] * rsqrtf(vv0[o] + 1e-3f);
        sm[S_W0 + c * 64 + o] = w0[o * 4 + c] * s;
    }
    for (int i = tid; i < 4096; i += MTHR) {   // W1 -> WA
        int c = i >> 6, o = i & 63;
        float s = ga1[o] * rsqrtf(vv1[o] + 1e-3f);
        sm[S_WA + i] = w1[o * 64 + c] * s;
    }
    for (int i = tid; i < 4096; i += MTHR) {   // W2 h=0 -> WB
        int c = i >> 6, o = i & 63;
        float s = ga2[o] * rsqrtf(vv2[o] + 1e-3f);
        sm[S_WB + i] = w2[o * 64 + c] * s;
    }
    __syncthreads();

    const int grp = tid & 63;           // token group (4 tokens)
    const int g   = tid >> 6;           // channel group (8 channels), 0..7
    const int gb  = g * 8;
    const size_t tokBase = (size_t)blockIdx.x * MT;

    u64 acc[16];                        // acc[t*4+p] = ch (gb+2p, gb+2p+1), token t

    // ================= layer 0: 4 -> 64 (feats straight from gmem) =========
    {
        float4 ft[4];
#pragma unroll
        for (int t = 0; t < 4; t++)
            ft[t] = ((const float4*)g_feats)[tokBase + grp * 4 + t];

        const u64* cb = (const u64*)(sm + S_C0) + g * 4;
#pragma unroll
        for (int t = 0; t < 4; t++)
#pragma unroll
            for (int p = 0; p < 4; p++) acc[t * 4 + p] = cb[p];
#pragma unroll
        for (int c = 0; c < 4; c++) {
            float v0 = (c == 0) ? ft[0].x : (c == 1) ? ft[0].y : (c == 2) ? ft[0].z : ft[0].w;
            float v1 = (c == 0) ? ft[1].x : (c == 1) ? ft[1].y : (c == 2) ? ft[1].z : ft[1].w;
            float v2 = (c == 0) ? ft[2].x : (c == 1) ? ft[2].y : (c == 2) ? ft[2].z : ft[2].w;
            float v3 = (c == 0) ? ft[3].x : (c == 1) ? ft[3].y : (c == 2) ? ft[3].z : ft[3].w;
            u64 a0 = pack2(v0), a1 = pack2(v1), a2 = pack2(v2), a3 = pack2(v3);
            const ulonglong2* wp = (const ulonglong2*)(sm + S_W0 + c * 64 + gb);
            ulonglong2 wA = wp[0], wB = wp[1];
            u64 wv[4] = {wA.x, wA.y, wB.x, wB.y};
#pragma unroll
            for (int p = 0; p < 4; p++) {
                acc[0 * 4 + p] = ffma2(wv[p], a0, acc[0 * 4 + p]);
                acc[1 * 4 + p] = ffma2(wv[p], a1, acc[1 * 4 + p]);
                acc[2 * 4 + p] = ffma2(wv[p], a2, acc[2 * 4 + p]);
                acc[3 * 4 + p] = ffma2(wv[p], a3, acc[3 * 4 + p]);
            }
        }
#pragma unroll
        for (int p = 0; p < 4; p++) {
            float x0, y0, x1, y1, x2, y2, x3, y3;
            unpack2(acc[0 * 4 + p], x0, y0);
            unpack2(acc[1 * 4 + p], x1, y1);
            unpack2(acc[2 * 4 + p], x2, y2);
            unpack2(acc[3 * 4 + p], x3, y3);
            float4 lo = make_float4(fmaxf(x0, 0.f), fmaxf(x1, 0.f), fmaxf(x2, 0.f), fmaxf(x3, 0.f));
            float4 hi = make_float4(fmaxf(y0, 0.f), fmaxf(y1, 0.f), fmaxf(y2, 0.f), fmaxf(y3, 0.f));
            *(float4*)(sAct + (gb + 2 * p)     * MT + grp * 4) = lo;
            *(float4*)(sAct + (gb + 2 * p + 1) * MT + grp * 4) = hi;
        }
        __syncthreads();
    }

    // ================= layer 1: 64 -> 64 =================
    {
        const u64* cb = (const u64*)(sm + S_C1) + g * 4;
#pragma unroll
        for (int t = 0; t < 4; t++)
#pragma unroll
            for (int p = 0; p < 4; p++) acc[t * 4 + p] = cb[p];
#pragma unroll 2
        for (int c = 0; c < 64; c++) {
            float4 a = *(const float4*)(sAct + c * MT + grp * 4);
            u64 a0 = pack2(a.x), a1 = pack2(a.y), a2 = pack2(a.z), a3 = pack2(a.w);
            const ulonglong2* wp = (const ulonglong2*)(sm + S_WA + c * 64 + gb);
            ulonglong2 wA = wp[0], wB = wp[1];
            u64 wv[4] = {wA.x, wA.y, wB.x, wB.y};
#pragma unroll
            for (int p = 0; p < 4; p++) {
                acc[0 * 4 + p] = ffma2(wv[p], a0, acc[0 * 4 + p]);
                acc[1 * 4 + p] = ffma2(wv[p], a1, acc[1 * 4 + p]);
                acc[2 * 4 + p] = ffma2(wv[p], a2, acc[2 * 4 + p]);
                acc[3 * 4 + p] = ffma2(wv[p], a3, acc[3 * 4 + p]);
            }
        }
        __syncthreads();   // all layer-1 reads (act + WA) done
#pragma unroll
        for (int p = 0; p < 4; p++) {
            float x0, y0, x1, y1, x2, y2, x3, y3;
            unpack2(acc[0 * 4 + p], x0, y0);
            unpack2(acc[1 * 4 + p], x1, y1);
            unpack2(acc[2 * 4 + p], x2, y2);
            unpack2(acc[3 * 4 + p], x3, y3);
            float4 lo = make_float4(fmaxf(x0, 0.f), fmaxf(x1, 0.f), fmaxf(x2, 0.f), fmaxf(x3, 0.f));
            float4 hi = make_float4(fmaxf(y0, 0.f), fmaxf(y1, 0.f), fmaxf(y2, 0.f), fmaxf(y3, 0.f));
            *(float4*)(sAct + (gb + 2 * p)     * MT + grp * 4) = lo;
            *(float4*)(sAct + (gb + 2 * p + 1) * MT + grp * 4) = hi;
        }
        // refold WA <- W2 h=1 (W1 is dead now)
        for (int i = tid; i < 4096; i += MTHR) {
            int c = i >> 6, o = i & 63;
            sm[S_WA + i] = w2[(o + 64) * 64 + c] * sm[S_SC2 + o];
        }
        __syncthreads();
    }

    // ================= layer 2: 64 -> 128 (h0 from WB, h1 from WA) =========
    float tmax0 = 0.f, tmax1 = 0.f, tmax2 = 0.f, tmax3 = 0.f;  // relu floor
#pragma unroll 1
    for (int h = 0; h < 2; h++) {
        const float* wbase = sm + (h == 0 ? S_WB : S_WA);
        const u64* cb = (const u64*)(sm + S_C2) + h * 32 + g * 4;
#pragma unroll
        for (int t = 0; t < 4; t++)
#pragma unroll
            for (int p = 0; p < 4; p++) acc[t * 4 + p] = cb[p];
#pragma unroll 2
        for (int c = 0; c < 64; c++) {
            float4 a = *(const float4*)(sAct + c * MT + grp * 4);
            u64 a0 = pack2(a.x), a1 = pack2(a.y), a2 = pack2(a.z), a3 = pack2(a.w);
            const ulonglong2* wp = (const ulonglong2*)(wbase + c * 64 + gb);
            ulonglong2 wA = wp[0], wB = wp[1];
            u64 wv[4] = {wA.x, wA.y, wB.x, wB.y};
#pragma unroll
            for (int p = 0; p < 4; p++) {
                acc[0 * 4 + p] = ffma2(wv[p], a0, acc[0 * 4 + p]);
                acc[1 * 4 + p] = ffma2(wv[p], a1, acc[1 * 4 + p]);
                acc[2 * 4 + p] = ffma2(wv[p], a2, acc[2 * 4 + p]);
                acc[3 * 4 + p] = ffma2(wv[p], a3, acc[3 * 4 + p]);
            }
        }
#pragma unroll
        for (int p = 0; p < 4; p++) {
            float lo, hi;
            unpack2(acc[0 * 4 + p], lo, hi); tmax0 = fmaxf(tmax0, fmaxf(lo, hi));
            unpack2(acc[1 * 4 + p], lo, hi); tmax1 = fmaxf(tmax1, fmaxf(lo, hi));
            unpack2(acc[2 * 4 + p], lo, hi); tmax2 = fmaxf(tmax2, fmaxf(lo, hi));
            unpack2(acc[3 * 4 + p], lo, hi); tmax3 = fmaxf(tmax3, fmaxf(lo, hi));
        }
    }
    __syncthreads();                    // act dead -> alias as max buffer [8][MT]
    sAct[g * MT + grp * 4 + 0] = tmax0;
    sAct[g * MT + grp * 4 + 1] = tmax1;
    sAct[g * MT + grp * 4 + 2] = tmax2;
    sAct[g * MT + grp * 4 + 3] = tmax3;
    __syncthreads();

    // ---- back to thread = token (first MT threads) ----
    if (tid < MT) {
        const int lane = tid & 31;
        const int wg = blockIdx.x * (MT / 32) + (tid >> 5);    // = b*NN + n
        const int b = wg >> 12;
        const int n = wg & (NN - 1);
        const float4 f = ((const float4*)g_feats)[tokBase + tid];

        float gmax = sAct[tid];
#pragma unroll
        for (int gg = 1; gg < 8; gg++) gmax = fmaxf(gmax, sAct[gg * MT + tid]);

        // ---- softmax over the 32 neighbors (one warp = one query) ----
        float m = gmax;
#pragma unroll
        for (int off = 16; off; off >>= 1) m = fmaxf(m, __shfl_xor_sync(FULL, m, off));
        float e = __expf(gmax - m);
        float ssum = e;
#pragma unroll
        for (int off = 16; off; off >>= 1) ssum += __shfl_xor_sync(FULL, ssum, off);
        float w = e / ssum;

        // out = q + sum_j w_j * resi_j   (since sum w = 1)
        float wx = w * f.x, wy = w * f.y, wz = w * f.z;
#pragma unroll
        for (int off = 16; off; off >>= 1) {
            wx += __shfl_xor_sync(FULL, wx, off);
            wy += __shfl_xor_sync(FULL, wy, off);
            wz += __shfl_xor_sync(FULL, wz, off);
        }
        if (lane == 0) {
            const float* qb = p1 + b * 3 * NN;
            out[b * 3 * NN + n]          = qb[n]          + wx;
            out[b * 3 * NN + NN + n]     = qb[NN + n]     + wy;
            out[b * 3 * NN + 2 * NN + n] = qb[2 * NN + n] + wz;
        }
    }
}

// ---------------- launch ---------------------------------------------------
extern "C" void kernel_launch(void* const* d_in, const int* in_sizes, int n_in,
                              void* d_out, int out_size)
{
    const float* p1 = (const float*)d_in[0];
    const float* p2 = (const float*)d_in[1];
    // d_in[2] = k (fixed at 16 for this shape)
    const float* w0 = (const float*)d_in[3];
    const float* b0 = (const float*)d_in[4];
    const float* g0 = (const float*)d_in[5];
    const float* e0 = (const float*)d_in[6];
    const float* m0 = (const float*)d_in[7];
    const float* v0 = (const float*)d_in[8];
    const float* w1 = (const float*)d_in[9];
    const float* b1 = (const float*)d_in[10];
    const float* g1 = (const float*)d_in[11];
    const float* e1 = (const float*)d_in[12];
    const float* m1 = (const float*)d_in[13];
    const float* v1 = (const float*)d_in[14];
    const float* w2 = (const float*)d_in[15];
    const float* b2 = (const float*)d_in[16];
    const float* g2 = (const float*)d_in[17];
    const float* e2 = (const float*)d_in[18];
    const float* m2 = (const float*)d_in[19];
    const float* v2 = (const float*)d_in[20];

    cudaFuncSetAttribute(mlp_kernel, cudaFuncAttributeMaxDynamicSharedMemorySize, SMEM_BYTES);
    cudaFuncSetAttribute(knn_kernel, cudaFuncAttributeMaxDynamicSharedMemorySize, NN * 16);

    knn_kernel<<<dim3(NN / 16, BB, 2), 512, NN * 16>>>(p1, p2);

    const int ntok = BB * NN * NB;              // 524288 tokens
    mlp_kernel<<<ntok / MT, MTHR, SMEM_BYTES>>>(
        p1, (float*)d_out,
        w0, b0, g0, e0, m0, v0,
        w1, b1, g1, e1, m1, v1,
        w2, b2, g2, e2, m2, v2);
}

// round 10
// speedup vs baseline: 1.0839x; 1.0839x over previous
#include <cuda_runtime.h>
#include <math.h>

#define BB 4
#define NN 4096
#define KK 16
#define NB 32          // 2k neighbors per query
#define FULL 0xffffffffu

typedef unsigned long long u64;

// ---------------- scratch (__device__ globals; no allocation allowed) -------
__device__ float g_feats[BB * NN * NB * 4];                 // {rx,ry,rz,dist} per token, 8MB

// ---------------- f32x2 helpers --------------------------------------------
__device__ __forceinline__ u64 ffma2(u64 a, u64 b, u64 c) {
    u64 d;
    asm("fma.rn.f32x2 %0, %1, %2, %3;" : "=l"(d) : "l"(a), "l"(b), "l"(c));
    return d;
}
__device__ __forceinline__ u64 pack2(float x) {
    u64 r;
    unsigned xu = __float_as_uint(x);
    asm("mov.b64 %0, {%1, %1};" : "=l"(r) : "r"(xu));
    return r;
}
__device__ __forceinline__ void unpack2(u64 v, float& lo, float& hi) {
    unsigned a, b;
    asm("mov.b64 {%0, %1}, %2;" : "=r"(a), "=r"(b) : "l"(v));
    lo = __uint_as_float(a);
    hi = __uint_as_float(b);
}

// ---------------- kNN: warp per query, warp-collective top-16 --------------
// (unchanged from best passing round)
__global__ __launch_bounds__(512) void knn_kernel(
    const float* __restrict__ p1, const float* __restrict__ p2)
{
    extern __shared__ float4 tile[];       // 4096 x {x,y,z,|r|^2}
    const int lane = threadIdx.x & 31;
    const int warp = threadIdx.x >> 5;
    const int b = blockIdx.y;
    const int set = blockIdx.z;

    const float* qb = p1 + b * 3 * NN;
    const float* rb = (set == 0 ? p1 : p2) + b * 3 * NN;

    for (int j = threadIdx.x; j < NN; j += 512) {
        float rx = rb[j], ry = rb[NN + j], rz = rb[2 * NN + j];
        tile[j] = make_float4(rx, ry, rz, rx * rx + ry * ry + rz * rz);
    }
    __syncthreads();

    const int qi = blockIdx.x * 16 + warp;
    const float qx = qb[qi], qy = qb[NN + qi], qz = qb[2 * NN + qi];
    const float qq = qx * qx + qy * qy + qz * qz;

    float ld;
    int   li;
    {
        float4 c = tile[lane];
        float dot = qx * c.x + qy * c.y + qz * c.z;
        ld = fmaf(-2.0f, dot, qq) + c.w;
        li = lane;
#pragma unroll
        for (int k = 2; k <= 32; k <<= 1) {
#pragma unroll
            for (int j = k >> 1; j > 0; j >>= 1) {
                float od = __shfl_xor_sync(FULL, ld, j);
                int   oi = __shfl_xor_sync(FULL, li, j);
                bool up    = ((lane & k) == 0);
                bool lower = ((lane & j) == 0);
                bool lt = (od < ld) || (od == ld && oi < li);
                bool takeOther = (lt == (lower == up));
                ld = takeOther ? od : ld;
                li = takeOther ? oi : li;
            }
        }
    }
    float thresh = __shfl_sync(FULL, ld, 15);

#pragma unroll 2
    for (int t = 1; t < NN / 32; t++) {
        const int j = t * 32 + lane;
        float4 c = tile[j];
        float dot = qx * c.x + qy * c.y + qz * c.z;
        float d2 = fmaf(-2.0f, dot, qq) + c.w;
        unsigned mask = __ballot_sync(FULL, d2 < thresh);
        if (mask) {
            do {
                int src = __ffs(mask) - 1;
                mask &= mask - 1;
                float xd = __shfl_sync(FULL, d2, src);
                int   xi = __shfl_sync(FULL, j, src);
                float pd = __shfl_up_sync(FULL, ld, 1);
                int   pi = __shfl_up_sync(FULL, li, 1);
                bool take  = (xd < ld);
                bool shift = (lane > 0) && (xd < pd);
                ld = take ? (shift ? pd : xd) : ld;
                li = take ? (shift ? pi : xi) : li;
            } while (mask);
            thresh = __shfl_sync(FULL, ld, 15);
        }
    }

    if (lane < KK) {
        float4 c = tile[li];
        float rx = c.x - qx, ry = c.y - qy, rz = c.z - qz;
        float d2r = rx * rx + ry * ry + rz * rz;
        float dist = sqrtf(fmaxf(d2r, 1e-12f));
        ((float4*)g_feats)[((size_t)(b * NN + qi)) * NB + set * KK + lane] =
            make_float4(rx, ry, rz, dist);
    }
}

// ---------------- fused fold + MLP + max + softmax + weighted sum ----------
// 256 threads per 256 tokens, thread = 8 output channels x 8 tokens:
//   warp = one channel group (g = tid>>5, ch 8g..8g+7)  -> weight LDS warp-uniform
//   lane = token group (tokens 8*lane .. 8*lane+7)
// acc = 32 u64 f32x2 (ch-pair packed): wf/FFMA2 = 16/32 = 0.5 (vs 0.625 R8).
// Act rows [64][256] with a 1-bit 16B-slot swizzle so 32B/lane strides stay
// bank-conflict-free at both store and load.
#define MT 256                      // tokens (= threads) per MLP block
#define S_W0  0
#define S_C0  256
#define S_C1  320
#define S_C2  384                   // 128 entries
#define S_SC2 512                   // 64 scales for out-ch 64..127 (refold)
#define S_WA  576                   // W1, then W2 h=1
#define S_WB  (S_WA + 4096)         // W2 h=0
#define S_ACT (S_WB + 4096)         // [64][MT]
#define SMEM_FLOATS (S_ACT + 64 * MT)
#define SMEM_BYTES  (SMEM_FLOATS * 4)

__global__ __launch_bounds__(MT, 2) void mlp_kernel(
    const float* __restrict__ p1, float* __restrict__ out,
    const float* __restrict__ w0, const float* __restrict__ b0,
    const float* __restrict__ ga0, const float* __restrict__ be0,
    const float* __restrict__ mm0, const float* __restrict__ vv0,
    const float* __restrict__ w1, const float* __restrict__ b1,
    const float* __restrict__ ga1, const float* __restrict__ be1,
    const float* __restrict__ mm1, const float* __restrict__ vv1,
    const float* __restrict__ w2, const float* __restrict__ b2,
    const float* __restrict__ ga2, const float* __restrict__ be2,
    const float* __restrict__ mm2, const float* __restrict__ vv2)
{
    extern __shared__ float sm[];
    float* sAct = sm + S_ACT;

    const int tid = threadIdx.x;

    // ---- in-block BN fold ----
    if (tid < 64) {
        float s = ga0[tid] * rsqrtf(vv0[tid] + 1e-3f);
        sm[S_C0 + tid] = (b0[tid] - mm0[tid]) * s + be0[tid];
    } else if (tid < 128) {
        int o = tid - 64;
        float s = ga1[o] * rsqrtf(vv1[o] + 1e-3f);
        sm[S_C1 + o] = (b1[o] - mm1[o]) * s + be1[o];
    } else {
        int o = tid - 128;
        float s = ga2[o] * rsqrtf(vv2[o] + 1e-3f);
        sm[S_C2 + o] = (b2[o] - mm2[o]) * s + be2[o];
        if (o >= 64) sm[S_SC2 + o - 64] = s;
    }
    {       // W0 [4][64]
        int c = tid >> 6, o = tid & 63;
        float s = ga0[o] * rsqrtf(vv0[o] + 1e-3f);
        sm[S_W0 + c * 64 + o] = w0[o * 4 + c] * s;
    }
    for (int i = tid; i < 4096; i += MT) {   // W1 -> WA
        int c = i >> 6, o = i & 63;
        float s = ga1[o] * rsqrtf(vv1[o] + 1e-3f);
        sm[S_WA + i] = w1[o * 64 + c] * s;
    }
    for (int i = tid; i < 4096; i += MT) {   // W2 h=0 -> WB
        int c = i >> 6, o = i & 63;
        float s = ga2[o] * rsqrtf(vv2[o] + 1e-3f);
        sm[S_WB + i] = w2[o * 64 + c] * s;
    }

    const int lane = tid & 31;          // token group (8 tokens)
    const int g    = tid >> 5;          // channel group (8 channels), warp-uniform
    const int gb   = g * 8;
    const size_t tokBase = (size_t)blockIdx.x * MT;

    // swizzled 16B-slot offsets (in floats) for this lane's two float4 slots
    const int swz   = (lane >> 2) & 1;
    const int slotA = ((2 * lane) ^ swz) * 4;       // tokens 8l..8l+3
    const int slotB = ((2 * lane + 1) ^ swz) * 4;   // tokens 8l+4..8l+7

    // ---- stage feats into act rows 0..3 (transposed, swizzled) ----
    {
        float4 ft[8];
#pragma unroll
        for (int t = 0; t < 8; t++)
            ft[t] = ((const float4*)g_feats)[tokBase + lane * 8 + t];
#pragma unroll
        for (int c = 0; c < 4; c++) {
            float4 A, B;
            A.x = (c==0)?ft[0].x:(c==1)?ft[0].y:(c==2)?ft[0].z:ft[0].w;
            A.y = (c==0)?ft[1].x:(c==1)?ft[1].y:(c==2)?ft[1].z:ft[1].w;
            A.z = (c==0)?ft[2].x:(c==1)?ft[2].y:(c==2)?ft[2].z:ft[2].w;
            A.w = (c==0)?ft[3].x:(c==1)?ft[3].y:(c==2)?ft[3].z:ft[3].w;
            B.x = (c==0)?ft[4].x:(c==1)?ft[4].y:(c==2)?ft[4].z:ft[4].w;
            B.y = (c==0)?ft[5].x:(c==1)?ft[5].y:(c==2)?ft[5].z:ft[5].w;
            B.z = (c==0)?ft[6].x:(c==1)?ft[6].y:(c==2)?ft[6].z:ft[6].w;
            B.w = (c==0)?ft[7].x:(c==1)?ft[7].y:(c==2)?ft[7].z:ft[7].w;
            *(float4*)(sAct + c * MT + slotA) = A;
            *(float4*)(sAct + c * MT + slotB) = B;
        }
    }
    __syncthreads();

    u64 acc[32];                        // acc[t*4+p] = ch (gb+2p, gb+2p+1), token t

#define GEMM_STEP(WBASE, C)                                                   \
    {                                                                         \
        const ulonglong2* wp = (const ulonglong2*)((WBASE) + (C) * 64 + gb);  \
        ulonglong2 wA = wp[0], wB = wp[1];                                    \
        u64 wv[4] = {wA.x, wA.y, wB.x, wB.y};                                 \
        float4 aA = *(const float4*)(sAct + (C) * MT + slotA);                \
        float4 aB = *(const float4*)(sAct + (C) * MT + slotB);                \
        u64 av[8] = {pack2(aA.x), pack2(aA.y), pack2(aA.z), pack2(aA.w),      \
                     pack2(aB.x), pack2(aB.y), pack2(aB.z), pack2(aB.w)};     \
        _Pragma("unroll")                                                     \
        for (int p = 0; p < 4; p++) {                                         \
            _Pragma("unroll")                                                 \
            for (int t = 0; t < 8; t++)                                       \
                acc[t * 4 + p] = ffma2(wv[p], av[t], acc[t * 4 + p]);         \
        }                                                                     \
    }

#define STORE_ACT()                                                           \
    {                                                                         \
        _Pragma("unroll")                                                     \
        for (int p = 0; p < 4; p++) {                                         \
            float lo[8], hi[8];                                               \
            _Pragma("unroll")                                                 \
            for (int t = 0; t < 8; t++) unpack2(acc[t * 4 + p], lo[t], hi[t]);\
            float4 A = make_float4(fmaxf(lo[0],0.f), fmaxf(lo[1],0.f),        \
                                   fmaxf(lo[2],0.f), fmaxf(lo[3],0.f));       \
            float4 B = make_float4(fmaxf(lo[4],0.f), fmaxf(lo[5],0.f),        \
                                   fmaxf(lo[6],0.f), fmaxf(lo[7],0.f));       \
            *(float4*)(sAct + (gb + 2*p) * MT + slotA) = A;                   \
            *(float4*)(sAct + (gb + 2*p) * MT + slotB) = B;                   \
            A = make_float4(fmaxf(hi[0],0.f), fmaxf(hi[1],0.f),               \
                            fmaxf(hi[2],0.f), fmaxf(hi[3],0.f));              \
            B = make_float4(fmaxf(hi[4],0.f), fmaxf(hi[5],0.f),               \
                            fmaxf(hi[6],0.f), fmaxf(hi[7],0.f));              \
            *(float4*)(sAct + (gb + 2*p + 1) * MT + slotA) = A;               \
            *(float4*)(sAct + (gb + 2*p + 1) * MT + slotB) = B;               \
        }                                                                     \
    }

    // ================= layer 0: 4 -> 64 =================
    {
        const u64* cb = (const u64*)(sm + S_C0) + g * 4;
#pragma unroll
        for (int t = 0; t < 8; t++)
#pragma unroll
            for (int p = 0; p < 4; p++) acc[t * 4 + p] = cb[p];
#pragma unroll
        for (int c = 0; c < 4; c++) GEMM_STEP(sm + S_W0, c)
        __syncthreads();               // feats rows read; safe to overwrite act
        STORE_ACT()
        __syncthreads();
    }

    // ================= layer 1: 64 -> 64 =================
    {
        const u64* cb = (const u64*)(sm + S_C1) + g * 4;
#pragma unroll
        for (int t = 0; t < 8; t++)
#pragma unroll
            for (int p = 0; p < 4; p++) acc[t * 4 + p] = cb[p];
#pragma unroll 2
        for (int c = 0; c < 64; c++) GEMM_STEP(sm + S_WA, c)
        __syncthreads();               // all layer-1 reads (act + WA) done
        STORE_ACT()
        // refold WA <- W2 h=1 (W1 is dead now)
        for (int i = tid; i < 4096; i += MT) {
            int c = i >> 6, o = i & 63;
            sm[S_WA + i] = w2[(o + 64) * 64 + c] * sm[S_SC2 + o];
        }
        __syncthreads();
    }

    // ================= layer 2: 64 -> 128 (h0 from WB, h1 from WA) =========
    float tm[8];
#pragma unroll
    for (int t = 0; t < 8; t++) tm[t] = 0.0f;   // relu floor
#pragma unroll 1
    for (int h = 0; h < 2; h++) {
        const float* wbase = sm + (h == 0 ? S_WB : S_WA);
        const u64* cb = (const u64*)(sm + S_C2) + h * 32 + g * 4;
#pragma unroll
        for (int t = 0; t < 8; t++)
#pragma unroll
            for (int p = 0; p < 4; p++) acc[t * 4 + p] = cb[p];
#pragma unroll 2
        for (int c = 0; c < 64; c++) GEMM_STEP(wbase, c)
#pragma unroll
        for (int p = 0; p < 4; p++)
#pragma unroll
            for (int t = 0; t < 8; t++) {
                float lo, hi;
                unpack2(acc[t * 4 + p], lo, hi);
                tm[t] = fmaxf(tm[t], fmaxf(lo, hi));
            }
    }
    __syncthreads();                    // act dead -> alias as max buffer [8][MT]
#pragma unroll
    for (int t = 0; t < 8; t++) sAct[g * MT + lane * 8 + t] = tm[t];
    __syncthreads();

    // ---- thread = token ----
    {
        const int wg = blockIdx.x * (MT / 32) + (tid >> 5);    // = b*NN + n
        const int b = wg >> 12;
        const int n = wg & (NN - 1);
        const float4 f = ((const float4*)g_feats)[tokBase + tid];

        float gmax = sAct[tid];
#pragma unroll
        for (int gg = 1; gg < 8; gg++) gmax = fmaxf(gmax, sAct[gg * MT + tid]);

        // ---- softmax over the 32 neighbors (one warp = one query) ----
        float m = gmax;
#pragma unroll
        for (int off = 16; off; off >>= 1) m = fmaxf(m, __shfl_xor_sync(FULL, m, off));
        float e = __expf(gmax - m);
        float ssum = e;
#pragma unroll
        for (int off = 16; off; off >>= 1) ssum += __shfl_xor_sync(FULL, ssum, off);
        float w = e / ssum;

        // out = q + sum_j w_j * resi_j   (since sum w = 1)
        float wx = w * f.x, wy = w * f.y, wz = w * f.z;
#pragma unroll
        for (int off = 16; off; off >>= 1) {
            wx += __shfl_xor_sync(FULL, wx, off);
            wy += __shfl_xor_sync(FULL, wy, off);
            wz += __shfl_xor_sync(FULL, wz, off);
        }
        if (lane == 0) {
            const float* qb = p1 + b * 3 * NN;
            out[b * 3 * NN + n]          = qb[n]          + wx;
            out[b * 3 * NN + NN + n]     = qb[NN + n]     + wy;
            out[b * 3 * NN + 2 * NN + n] = qb[2 * NN + n] + wz;
        }
    }
}

// ---------------- launch ---------------------------------------------------
extern "C" void kernel_launch(void* const* d_in, const int* in_sizes, int n_in,
                              void* d_out, int out_size)
{
    const float* p1 = (const float*)d_in[0];
    const float* p2 = (const float*)d_in[1];
    // d_in[2] = k (fixed at 16 for this shape)
    const float* w0 = (const float*)d_in[3];
    const float* b0 = (const float*)d_in[4];
    const float* g0 = (const float*)d_in[5];
    const float* e0 = (const float*)d_in[6];
    const float* m0 = (const float*)d_in[7];
    const float* v0 = (const float*)d_in[8];
    const float* w1 = (const float*)d_in[9];
    const float* b1 = (const float*)d_in[10];
    const float* g1 = (const float*)d_in[11];
    const float* e1 = (const float*)d_in[12];
    const float* m1 = (const float*)d_in[13];
    const float* v1 = (const float*)d_in[14];
    const float* w2 = (const float*)d_in[15];
    const float* b2 = (const float*)d_in[16];
    const float* g2 = (const float*)d_in[17];
    const float* e2 = (const float*)d_in[18];
    const float* m2 = (const float*)d_in[19];
    const float* v2 = (const float*)d_in[20];

    cudaFuncSetAttribute(mlp_kernel, cudaFuncAttributeMaxDynamicSharedMemorySize, SMEM_BYTES);
    cudaFuncSetAttribute(knn_kernel, cudaFuncAttributeMaxDynamicSharedMemorySize, NN * 16);

    knn_kernel<<<dim3(NN / 16, BB, 2), 512, NN * 16>>>(p1, p2);

    const int ntok = BB * NN * NB;              // 524288 tokens
    mlp_kernel<<<ntok / MT, MT, SMEM_BYTES>>>(
        p1, (float*)d_out,
        w0, b0, g0, e0, m0, v0,
        w1, b1, g1, e1, m1, v1,
        w2, b2, g2, e2, m2, v2);
}

// round 12
// speedup vs baseline: 1.8470x; 1.7041x over previous
#include <cuda_runtime.h>
#include <cuda_bf16.h>
#include <math.h>
#include <stdint.h>

#define BB 4
#define NN 4096
#define KK 16
#define NB 32          // 2k neighbors per query
#define FULL 0xffffffffu

// ---------------- scratch (__device__ globals; no allocation allowed) -------
__device__ float g_feats[BB * NN * NB * 4];   // {rx,ry,rz,dist} per token, 8MB
// pre-folded, bf16-split, PRE-SWIZZLED weight tiles (64KB) + fp32 biases
__device__ uint4 g_wt4[4096];                 // bf16[32768]
__device__ float g_bias[256];                 // C0[0:64) C1[64:128) C2[128:256)

// bf16-unit offsets inside g_wt (prep writes)
#define WT_W0HI 0
#define WT_W0LO 4096
#define WT_W1HI 8192
#define WT_W1LO 12288
#define WT_W2HI 16384
#define WT_W2LO 24576
// byte offsets inside the smem weight block (mlp reads)
#define WB_W0HI 0
#define WB_W0LO 8192
#define WB_W1HI 16384
#define WB_W1LO 24576
#define WB_W2HI 32768
#define WB_W2LO 49152

// ---------------- small helpers --------------------------------------------
#define SWZ(b) ((b) ^ (((b) >> 3) & 0x70))

__device__ __forceinline__ uint32_t smem_u32(const void* p) {
    uint32_t a;
    asm("{ .reg .u64 t; cvta.to.shared.u64 t, %1; cvt.u32.u64 %0, t; }"
        : "=r"(a) : "l"(p));
    return a;
}
__device__ __forceinline__ void bsplit(float x, __nv_bfloat16& h, __nv_bfloat16& l) {
    h = __float2bfloat16(x);
    l = __float2bfloat16(x - __bfloat162float(h));
}
__device__ __forceinline__ uint32_t bpack(__nv_bfloat16 a, __nv_bfloat16 b) {
    return (uint32_t)__bfloat16_as_ushort(a) | ((uint32_t)__bfloat16_as_ushort(b) << 16);
}

// ---------------- mma.sync / ldmatrix wrappers (sm_80 features) -------------
__device__ __forceinline__ void ldsm_x4(uint32_t* r, uint32_t addr) {
    asm volatile("ldmatrix.sync.aligned.m8n8.x4.shared.b16 {%0,%1,%2,%3}, [%4];"
                 : "=r"(r[0]), "=r"(r[1]), "=r"(r[2]), "=r"(r[3]) : "r"(addr));
}
__device__ __forceinline__ void ldsm_x2(uint32_t* r, uint32_t addr) {
    asm volatile("ldmatrix.sync.aligned.m8n8.x2.shared.b16 {%0,%1}, [%2];"
                 : "=r"(r[0]), "=r"(r[1]) : "r"(addr));
}
__device__ __forceinline__ void mma_bf16(float* c, const uint32_t* a, const uint32_t* b) {
    asm volatile("mma.sync.aligned.m16n8k16.row.col.f32.bf16.bf16.f32 "
                 "{%0,%1,%2,%3}, {%4,%5,%6,%7}, {%8,%9}, {%0,%1,%2,%3};"
                 : "+f"(c[0]), "+f"(c[1]), "+f"(c[2]), "+f"(c[3])
                 : "r"(a[0]), "r"(a[1]), "r"(a[2]), "r"(a[3]),
                   "r"(b[0]), "r"(b[1]));
}

// ---------------- kNN: warp per query, warp-collective top-16 (unchanged) ---
__global__ __launch_bounds__(512) void knn_kernel(
    const float* __restrict__ p1, const float* __restrict__ p2)
{
    extern __shared__ float4 tile[];       // 4096 x {x,y,z,|r|^2}
    const int lane = threadIdx.x & 31;
    const int warp = threadIdx.x >> 5;
    const int b = blockIdx.y;
    const int set = blockIdx.z;

    const float* qb = p1 + b * 3 * NN;
    const float* rb = (set == 0 ? p1 : p2) + b * 3 * NN;

    for (int j = threadIdx.x; j < NN; j += 512) {
        float rx = rb[j], ry = rb[NN + j], rz = rb[2 * NN + j];
        tile[j] = make_float4(rx, ry, rz, rx * rx + ry * ry + rz * rz);
    }
    __syncthreads();

    const int qi = blockIdx.x * 16 + warp;
    const float qx = qb[qi], qy = qb[NN + qi], qz = qb[2 * NN + qi];
    const float qq = qx * qx + qy * qy + qz * qz;

    float ld;
    int   li;
    {
        float4 c = tile[lane];
        float dot = qx * c.x + qy * c.y + qz * c.z;
        ld = fmaf(-2.0f, dot, qq) + c.w;
        li = lane;
#pragma unroll
        for (int k = 2; k <= 32; k <<= 1) {
#pragma unroll
            for (int j = k >> 1; j > 0; j >>= 1) {
                float od = __shfl_xor_sync(FULL, ld, j);
                int   oi = __shfl_xor_sync(FULL, li, j);
                bool up    = ((lane & k) == 0);
                bool lower = ((lane & j) == 0);
                bool lt = (od < ld) || (od == ld && oi < li);
                bool takeOther = (lt == (lower == up));
                ld = takeOther ? od : ld;
                li = takeOther ? oi : li;
            }
        }
    }
    float thresh = __shfl_sync(FULL, ld, 15);

#pragma unroll 2
    for (int t = 1; t < NN / 32; t++) {
        const int j = t * 32 + lane;
        float4 c = tile[j];
        float dot = qx * c.x + qy * c.y + qz * c.z;
        float d2 = fmaf(-2.0f, dot, qq) + c.w;
        unsigned mask = __ballot_sync(FULL, d2 < thresh);
        if (mask) {
            do {
                int src = __ffs(mask) - 1;
                mask &= mask - 1;
                float xd = __shfl_sync(FULL, d2, src);
                int   xi = __shfl_sync(FULL, j, src);
                float pd = __shfl_up_sync(FULL, ld, 1);
                int   pi = __shfl_up_sync(FULL, li, 1);
                bool take  = (xd < ld);
                bool shift = (lane > 0) && (xd < pd);
                ld = take ? (shift ? pd : xd) : ld;
                li = take ? (shift ? pi : xi) : li;
            } while (mask);
            thresh = __shfl_sync(FULL, ld, 15);
        }
    }

    if (lane < KK) {
        float4 c = tile[li];
        float rx = c.x - qx, ry = c.y - qy, rz = c.z - qz;
        float d2r = rx * rx + ry * ry + rz * rz;
        float dist = sqrtf(fmaxf(d2r, 1e-12f));
        ((float4*)g_feats)[((size_t)(b * NN + qi)) * NB + set * KK + lane] =
            make_float4(rx, ry, rz, dist);
    }
}

// ---------------- prep: fold BN, bf16-split, pre-swizzle weight tiles -------
__global__ void prep_kernel(
    const float* __restrict__ w0, const float* __restrict__ b0,
    const float* __restrict__ ga0, const float* __restrict__ be0,
    const float* __restrict__ mm0, const float* __restrict__ vv0,
    const float* __restrict__ w1, const float* __restrict__ b1,
    const float* __restrict__ ga1, const float* __restrict__ be1,
    const float* __restrict__ mm1, const float* __restrict__ vv1,
    const float* __restrict__ w2, const float* __restrict__ b2,
    const float* __restrict__ ga2, const float* __restrict__ be2,
    const float* __restrict__ mm2, const float* __restrict__ vv2)
{
    const int bid = blockIdx.x, tid = threadIdx.x;
    __nv_bfloat16* gw = reinterpret_cast<__nv_bfloat16*>(g_wt4);
    if (bid == 0) {
        for (int i = tid; i < 8192; i += 256) gw[i] = __float2bfloat16(0.0f);
        __syncthreads();
        {   // W0 [o<64][c<4] -> tile rows o (128B), cols c (K padded with zeros)
            int o = tid >> 2, c = tid & 3;
            float s = ga0[o] * rsqrtf(vv0[o] + 1e-3f);
            float wf = w0[o * 4 + c] * s;
            __nv_bfloat16 h, l; bsplit(wf, h, l);
            int pos = SWZ(o * 128 + c * 2) >> 1;
            gw[WT_W0HI + pos] = h;
            gw[WT_W0LO + pos] = l;
        }
        if (tid < 64) {
            float s = ga0[tid] * rsqrtf(vv0[tid] + 1e-3f);
            g_bias[tid] = (b0[tid] - mm0[tid]) * s + be0[tid];
        } else if (tid < 128) {
            int o = tid - 64;
            float s = ga1[o] * rsqrtf(vv1[o] + 1e-3f);
            g_bias[tid] = (b1[o] - mm1[o]) * s + be1[o];
        } else {
            int o = tid - 128;
            float s = ga2[o] * rsqrtf(vv2[o] + 1e-3f);
            g_bias[tid] = (b2[o] - mm2[o]) * s + be2[o];
        }
    } else if (bid <= 16) {
        int j = (bid - 1) * 256 + tid;       // < 4096
        int o = j >> 6, c = j & 63;
        float s = ga1[o] * rsqrtf(vv1[o] + 1e-3f);
        float wf = w1[o * 64 + c] * s;
        __nv_bfloat16 h, l; bsplit(wf, h, l);
        int pos = SWZ(o * 128 + c * 2) >> 1;
        gw[WT_W1HI + pos] = h;
        gw[WT_W1LO + pos] = l;
    } else {
        int j = (bid - 17) * 256 + tid;      // < 8192
        int o = j >> 6, c = j & 63;
        float s = ga2[o] * rsqrtf(vv2[o] + 1e-3f);
        float wf = w2[o * 64 + c] * s;
        __nv_bfloat16 h, l; bsplit(wf, h, l);
        int pos = SWZ(o * 128 + c * 2) >> 1;
        gw[WT_W2HI + pos] = h;
        gw[WT_W2LO + pos] = l;
    }
}

// ---------------- mma.sync MLP: 128 tokens/CTA, 3-term bf16-split -----------
// warp = one m16 token tile (8 warps). A act tiles [tok][128B] SW128 hi/lo;
// B weight tiles [ch][128B] SW128 (pre-swizzled). No __syncthreads in the
// main body: each warp's A rows are private; warp-sync mma orders in-place
// act updates (plus __syncwarp for cross-lane STS->LDSM visibility).
#define SM_AHI  0
#define SM_ALO  16384
#define SM_W    32768
#define SM_BIAS 98304
#define SM_GMAX 99328
#define SM_TOTAL (99840 + 1024)

// 64x64 GEMM tile: acc[8 ntiles][4], 3-term split, K=64 (4 k-steps)
__device__ __forceinline__ void gemm64(float (&acc)[8][4],
                                       uint32_t aHi, uint32_t aLo,
                                       uint32_t wHi, uint32_t wLo,
                                       int m0, int lane)
{
    uint32_t ah[16], al[16];
#pragma unroll
    for (int kk = 0; kk < 4; kk++) {
        uint32_t arow = (uint32_t)(m0 + (lane & 15)) * 128 + kk * 32 + ((lane >> 4) & 1) * 16;
        ldsm_x4(ah + kk * 4, aHi + SWZ(arow));
        ldsm_x4(al + kk * 4, aLo + SWZ(arow));
    }
#pragma unroll
    for (int nt = 0; nt < 8; nt++) {
#pragma unroll
        for (int kp = 0; kp < 2; kp++) {
            uint32_t boff = (uint32_t)(nt * 8 + (lane & 7)) * 128 + kp * 64 + (lane >> 3) * 16;
            uint32_t bh[4], bl[4];
            ldsm_x4(bh, wHi + SWZ(boff));
            ldsm_x4(bl, wLo + SWZ(boff));
            mma_bf16(acc[nt], ah + 8 * kp,     bh);
            mma_bf16(acc[nt], ah + 8 * kp,     bl);
            mma_bf16(acc[nt], al + 8 * kp,     bh);
            mma_bf16(acc[nt], ah + 8 * kp + 4, bh + 2);
            mma_bf16(acc[nt], ah + 8 * kp + 4, bl + 2);
            mma_bf16(acc[nt], al + 8 * kp + 4, bh + 2);
        }
    }
}

__global__ __launch_bounds__(256, 2) void mlp_mma_kernel(
    const float* __restrict__ p1, float* __restrict__ out)
{
    extern __shared__ char dsm[];
    const uint32_t base0 = smem_u32(dsm);
    const uint32_t base = (base0 + 1023u) & ~1023u;
    char* sm = dsm + (base - base0);

    const int tid = threadIdx.x;
    const int wid = tid >> 5;
    const int lane = tid & 31;
    const int m0 = wid * 16;

    // copy weights + biases into smem
    {
        uint4* dst = (uint4*)(sm + SM_W);
#pragma unroll 4
        for (int i = tid; i < 4096; i += 256) dst[i] = g_wt4[i];
        ((float*)(sm + SM_BIAS))[tid] = g_bias[tid];
    }

    // stage layer-0 A tiles: row = token (128B), k0-3 data, k4-15 zero
    const int tok0 = blockIdx.x * 128;
    if (tid < 128) {
        float4 f = ((const float4*)g_feats)[tok0 + tid];
        __nv_bfloat16 h0, l0, h1, l1, h2, l2, h3, l3;
        bsplit(f.x, h0, l0); bsplit(f.y, h1, l1);
        bsplit(f.z, h2, l2); bsplit(f.w, h3, l3);
        uint32_t ro = (uint32_t)tid * 128;
        *(uint4*)(sm + SM_AHI + SWZ(ro))      = make_uint4(bpack(h0, h1), bpack(h2, h3), 0u, 0u);
        *(uint4*)(sm + SM_AHI + SWZ(ro + 16)) = make_uint4(0u, 0u, 0u, 0u);
        *(uint4*)(sm + SM_ALO + SWZ(ro))      = make_uint4(bpack(l0, l1), bpack(l2, l3), 0u, 0u);
        *(uint4*)(sm + SM_ALO + SWZ(ro + 16)) = make_uint4(0u, 0u, 0u, 0u);
    }
    __syncthreads();

    const uint32_t aHi = base + SM_AHI;
    const uint32_t aLo = base + SM_ALO;
    const uint32_t wB  = base + SM_W;
    const float* sb = (const float*)(sm + SM_BIAS);

    float acc[8][4];

    // ---------------- layer 0: K=16 (single k-step) ----------------
    {
        uint32_t arow = (uint32_t)(m0 + (lane & 15)) * 128 + ((lane >> 4) & 1) * 16;
        uint32_t ah[4], al[4];
        ldsm_x4(ah, aHi + SWZ(arow));
        ldsm_x4(al, aLo + SWZ(arow));
#pragma unroll
        for (int nt = 0; nt < 8; nt++) {
#pragma unroll
            for (int i = 0; i < 4; i++) acc[nt][i] = 0.0f;
            uint32_t boff = (uint32_t)(nt * 8 + (lane & 7)) * 128 + ((lane >> 3) & 1) * 16;
            uint32_t bh[2], bl[2];
            ldsm_x2(bh, wB + WB_W0HI + SWZ(boff));
            ldsm_x2(bl, wB + WB_W0LO + SWZ(boff));
            mma_bf16(acc[nt], ah, bh);
            mma_bf16(acc[nt], ah, bl);
            mma_bf16(acc[nt], al, bh);
        }
    }
    // epilogue: bias + relu + split -> act (in place; warp-private rows)
#pragma unroll
    for (int nt = 0; nt < 8; nt++) {
        float2 b2 = *(const float2*)(sb + nt * 8 + (lane & 3) * 2);
        float v0 = fmaxf(acc[nt][0] + b2.x, 0.f);
        float v1 = fmaxf(acc[nt][1] + b2.y, 0.f);
        float v2 = fmaxf(acc[nt][2] + b2.x, 0.f);
        float v3 = fmaxf(acc[nt][3] + b2.y, 0.f);
        __nv_bfloat16 h0, l0, h1, l1, h2, l2, h3, l3;
        bsplit(v0, h0, l0); bsplit(v1, h1, l1);
        bsplit(v2, h2, l2); bsplit(v3, h3, l3);
        uint32_t r0b = (uint32_t)(m0 + (lane >> 2)) * 128 + nt * 16 + (lane & 3) * 4;
        uint32_t r1b = r0b + 8 * 128;
        *(uint32_t*)(sm + SM_AHI + SWZ(r0b)) = bpack(h0, h1);
        *(uint32_t*)(sm + SM_ALO + SWZ(r0b)) = bpack(l0, l1);
        *(uint32_t*)(sm + SM_AHI + SWZ(r1b)) = bpack(h2, h3);
        *(uint32_t*)(sm + SM_ALO + SWZ(r1b)) = bpack(l2, l3);
    }
    __syncwarp();

    // ---------------- layer 1: 64 -> 64 ----------------
#pragma unroll
    for (int nt = 0; nt < 8; nt++)
#pragma unroll
        for (int i = 0; i < 4; i++) acc[nt][i] = 0.0f;
    gemm64(acc, aHi, aLo, wB + WB_W1HI, wB + WB_W1LO, m0, lane);
#pragma unroll
    for (int nt = 0; nt < 8; nt++) {
        float2 b2 = *(const float2*)(sb + 64 + nt * 8 + (lane & 3) * 2);
        float v0 = fmaxf(acc[nt][0] + b2.x, 0.f);
        float v1 = fmaxf(acc[nt][1] + b2.y, 0.f);
        float v2 = fmaxf(acc[nt][2] + b2.x, 0.f);
        float v3 = fmaxf(acc[nt][3] + b2.y, 0.f);
        __nv_bfloat16 h0, l0, h1, l1, h2, l2, h3, l3;
        bsplit(v0, h0, l0); bsplit(v1, h1, l1);
        bsplit(v2, h2, l2); bsplit(v3, h3, l3);
        uint32_t r0b = (uint32_t)(m0 + (lane >> 2)) * 128 + nt * 16 + (lane & 3) * 4;
        uint32_t r1b = r0b + 8 * 128;
        *(uint32_t*)(sm + SM_AHI + SWZ(r0b)) = bpack(h0, h1);
        *(uint32_t*)(sm + SM_ALO + SWZ(r0b)) = bpack(l0, l1);
        *(uint32_t*)(sm + SM_AHI + SWZ(r1b)) = bpack(h2, h3);
        *(uint32_t*)(sm + SM_ALO + SWZ(r1b)) = bpack(l2, l3);
    }
    __syncwarp();

    // ---------------- layer 2: 64 -> 128 (two N=64 halves), channel max ----
    float tmA = 0.0f, tmB = 0.0f;   // relu floor = 0
#pragma unroll 1
    for (int h = 0; h < 2; h++) {
#pragma unroll
        for (int nt = 0; nt < 8; nt++)
#pragma unroll
            for (int i = 0; i < 4; i++) acc[nt][i] = 0.0f;
        gemm64(acc, aHi, aLo, wB + WB_W2HI + h * 8192, wB + WB_W2LO + h * 8192, m0, lane);
#pragma unroll
        for (int nt = 0; nt < 8; nt++) {
            float2 b2 = *(const float2*)(sb + 128 + h * 64 + nt * 8 + (lane & 3) * 2);
            tmA = fmaxf(tmA, fmaxf(acc[nt][0] + b2.x, acc[nt][1] + b2.y));
            tmB = fmaxf(tmB, fmaxf(acc[nt][2] + b2.x, acc[nt][3] + b2.y));
        }
    }
    // reduce across the 4 lanes sharing each token row
    tmA = fmaxf(tmA, __shfl_xor_sync(FULL, tmA, 1));
    tmA = fmaxf(tmA, __shfl_xor_sync(FULL, tmA, 2));
    tmB = fmaxf(tmB, __shfl_xor_sync(FULL, tmB, 1));
    tmB = fmaxf(tmB, __shfl_xor_sync(FULL, tmB, 2));
    {
        float* gm = (float*)(sm + SM_GMAX);
        if ((lane & 3) == 0) {
            gm[m0 + (lane >> 2)]     = tmA;
            gm[m0 + 8 + (lane >> 2)] = tmB;
        }
    }
    __syncthreads();

    // ---------------- softmax (warp = query) + weighted sum ----------------
    if (tid < 128) {
        const float* gm = (const float*)(sm + SM_GMAX);
        float gmax = gm[tid];

        float m = gmax;
#pragma unroll
        for (int off = 16; off; off >>= 1) m = fmaxf(m, __shfl_xor_sync(FULL, m, off));
        float e = __expf(gmax - m);
        float ssum = e;
#pragma unroll
        for (int off = 16; off; off >>= 1) ssum += __shfl_xor_sync(FULL, ssum, off);
        float w = e / ssum;

        float4 f = ((const float4*)g_feats)[tok0 + tid];
        float wx = w * f.x, wy = w * f.y, wz = w * f.z;
#pragma unroll
        for (int off = 16; off; off >>= 1) {
            wx += __shfl_xor_sync(FULL, wx, off);
            wy += __shfl_xor_sync(FULL, wy, off);
            wz += __shfl_xor_sync(FULL, wz, off);
        }
        if (lane == 0) {
            const int wg = blockIdx.x * 4 + (tid >> 5);   // = b*NN + n
            const int b = wg >> 12;
            const int n = wg & (NN - 1);
            const float* qb = p1 + b * 3 * NN;
            out[b * 3 * NN + n]          = qb[n]          + wx;
            out[b * 3 * NN + NN + n]     = qb[NN + n]     + wy;
            out[b * 3 * NN + 2 * NN + n] = qb[2 * NN + n] + wz;
        }
    }
}

// ---------------- launch ---------------------------------------------------
extern "C" void kernel_launch(void* const* d_in, const int* in_sizes, int n_in,
                              void* d_out, int out_size)
{
    const float* p1 = (const float*)d_in[0];
    const float* p2 = (const float*)d_in[1];
    // d_in[2] = k (fixed at 16 for this shape)
    const float* w0 = (const float*)d_in[3];
    const float* b0 = (const float*)d_in[4];
    const float* g0 = (const float*)d_in[5];
    const float* e0 = (const float*)d_in[6];
    const float* m0 = (const float*)d_in[7];
    const float* v0 = (const float*)d_in[8];
    const float* w1 = (const float*)d_in[9];
    const float* b1 = (const float*)d_in[10];
    const float* g1 = (const float*)d_in[11];
    const float* e1 = (const float*)d_in[12];
    const float* m1 = (const float*)d_in[13];
    const float* v1 = (const float*)d_in[14];
    const float* w2 = (const float*)d_in[15];
    const float* b2 = (const float*)d_in[16];
    const float* g2 = (const float*)d_in[17];
    const float* e2 = (const float*)d_in[18];
    const float* m2 = (const float*)d_in[19];
    const float* v2 = (const float*)d_in[20];

    cudaFuncSetAttribute(knn_kernel, cudaFuncAttributeMaxDynamicSharedMemorySize, NN * 16);
    cudaFuncSetAttribute(mlp_mma_kernel, cudaFuncAttributeMaxDynamicSharedMemorySize, SM_TOTAL);

    prep_kernel<<<49, 256>>>(w0, b0, g0, e0, m0, v0,
                             w1, b1, g1, e1, m1, v1,
                             w2, b2, g2, e2, m2, v2);

    knn_kernel<<<dim3(NN / 16, BB, 2), 512, NN * 16>>>(p1, p2);

    mlp_mma_kernel<<<BB * NN * NB / 128, 256, SM_TOTAL>>>(p1, (float*)d_out);
}